// round 3
// baseline (speedup 1.0000x reference)
#include <cuda_runtime.h>
#include <cstdint>

// Problem constants (fixed by the dataset)
#define H   1024
#define LL  4
#define BB  128
#define SS  512
#define VV  128

// Shared layouts in recur_kernel:
//  comb_all: [0,1024) n (m-block only), [1024,2048) h copy0,
//            [2048, 2048+1056) h copy1 skewed: addr = 2048 + j + (j>>5), j = h-local idx
//  t_all:    [0,1024) copy0; [1024, 1024+1056) copy1 skewed: addr = 1024 + i + (i>>5)
#define COMB_ALL_SZ 3104
#define T_ALL_SZ    2080

// ---------------------------------------------------------------------------
// Scratch (device globals — no allocation allowed in kernel_launch)
// ---------------------------------------------------------------------------
__device__ float4   g_cn [LL*H];
__device__ float4   g_ck [LL*H];
__device__ float4   g_cm [LL*H];
__device__ float4   g_cmf[2*H];
__device__ unsigned g_in [LL*H];
__device__ unsigned g_ik [LL*H];
__device__ unsigned g_im [LL*H];
__device__ unsigned g_imf[2*H];
__device__ float    g_ntab[VV*H];      // n-branch output per token

// Fused k super-layers
__device__ float    g_fkc_raw[2*H*16]; // canonical multilinear coeffs
__device__ uint2    g_fki[2*H];        // raw logical indices (4 x 16-bit)
__device__ float4   g_fkc[2*H*4];      // slot-permuted coeffs (final)
__device__ uint2    g_fka[2*H];        // physical smem addresses (4 x 16-bit)
__device__ unsigned g_msk[2*H];        // per-slot "is n-leaf" mask (layer1 only)
__device__ unsigned g_perm[2*H];       // varOfSlot, 2 bits per slot
__device__ uint2    g_l1i[2*H];        // layer1 n-leaf original indices per slot
__device__ float4   g_nleaf[VV*H];     // per-token layer1 n-leaf values, slot order

// ---------------------------------------------------------------------------
// Kernel A: softmax(w) -> affine gate coefficients, pack gather indices.
// ---------------------------------------------------------------------------
__global__ void precompute_coef(
    const float* __restrict__ n_w, const float* __restrict__ k_w,
    const float* __restrict__ m_w, const float* __restrict__ mf_w,
    const int* __restrict__ n_idx, const int* __restrict__ k_idx0,
    const int* __restrict__ k_idx_rest, const int* __restrict__ m_idx0,
    const int* __restrict__ m_idx_rest, const int* __restrict__ m_idx_fin)
{
    int g = blockIdx.x * blockDim.x + threadIdx.x;
    const int NG = 3 * LL * H + 2 * H;
    if (g >= NG) return;

    const float* w; int i0, i1; float4* cdst; unsigned* idst; int slot;
    if (g < LL * H) {
        int l = g >> 10, o = g & (H - 1);
        w = n_w + (l * H + o) * 16;
        i0 = n_idx[(l * 2 + 0) * H + o];
        i1 = n_idx[(l * 2 + 1) * H + o];
        cdst = g_cn; idst = g_in; slot = g;
    } else if (g < 2 * LL * H) {
        int gg = g - LL * H, l = gg >> 10, o = gg & (H - 1);
        w = k_w + (l * H + o) * 16;
        if (l == 0) { i0 = k_idx0[o]; i1 = k_idx0[H + o]; }
        else        { i0 = k_idx_rest[((l - 1) * 2 + 0) * H + o];
                      i1 = k_idx_rest[((l - 1) * 2 + 1) * H + o]; }
        cdst = g_ck; idst = g_ik; slot = gg;
    } else if (g < 3 * LL * H) {
        int gg = g - 2 * LL * H, l = gg >> 10, o = gg & (H - 1);
        w = m_w + (l * H + o) * 16;
        if (l == 0) { i0 = m_idx0[o]; i1 = m_idx0[H + o]; }
        else        { i0 = m_idx_rest[((l - 1) * 2 + 0) * H + o];
                      i1 = m_idx_rest[((l - 1) * 2 + 1) * H + o]; }
        cdst = g_cm; idst = g_im; slot = gg;
    } else {
        int j = g - 3 * LL * H;
        w = mf_w + j * 16;
        i0 = m_idx_fin[j]; i1 = m_idx_fin[2 * H + j];
        cdst = g_cmf; idst = g_imf; slot = j;
    }

    float p[16], mx = w[0];
#pragma unroll
    for (int i = 1; i < 16; i++) mx = fmaxf(mx, w[i]);
    float s = 0.f;
#pragma unroll
    for (int i = 0; i < 16; i++) { p[i] = expf(w[i] - mx); s += p[i]; }
    float inv = 1.0f / s;
#pragma unroll
    for (int i = 0; i < 16; i++) p[i] *= inv;

    float c0 = p[8] + p[9] + p[10] + p[11] + p[12] + p[13] + p[14] + p[15];
    float c1 = p[2] + p[3] + p[6] + p[7] - p[8] - p[9] - p[12] - p[13];
    float c2 = p[4] + p[5] + p[6] + p[7] - p[8] - p[9] - p[10] - p[11];
    float c3 = p[1] - p[2] - p[4] - 2.f * p[6] - p[7]
             + p[8] + 2.f * p[9] + p[11] + p[13] - p[14];

    cdst[slot] = make_float4(c0, c1, c2, c3);
    idst[slot] = (unsigned)i0 | ((unsigned)i1 << 16);
}

// ---------------------------------------------------------------------------
// Kernel B: N_table[v] = n-branch(sigmoid(emb_table[v]))
// ---------------------------------------------------------------------------
__global__ __launch_bounds__(H) void precompute_ntab(const float* __restrict__ emb_table)
{
    __shared__ float b0[H], b1[H];
    int v = blockIdx.x, tid = threadIdx.x;
    float e = emb_table[v * H + tid];
    b0[tid] = 1.0f / (1.0f + expf(-e));
    __syncthreads();
    float* src = b0; float* dst = b1;
#pragma unroll
    for (int l = 0; l < LL; l++) {
        float4  c  = g_cn[l * H + tid];
        unsigned pi = g_in[l * H + tid];
        float a = src[pi & 0xFFFFu], b = src[pi >> 16];
        dst[tid] = fmaf(c.w, a * b, fmaf(c.z, b, fmaf(c.y, a, c.x)));
        __syncthreads();
        float* t = src; src = dst; dst = t;
    }
    g_ntab[v * H + tid] = src[tid];
}

// ---------------------------------------------------------------------------
// Kernel F: fuse k-layer pairs (0,1) and (2,3) into multilinear super-gates.
// ---------------------------------------------------------------------------
__global__ void fuse_k()
{
    int g = blockIdx.x * blockDim.x + threadIdx.x;
    if (g >= 2 * H) return;
    int sl = g >> 10, o = g & (H - 1);

    float4   e  = g_ck[(2 * sl + 1) * H + o];
    unsigned pq = g_ik[(2 * sl + 1) * H + o];
    int p = pq & 0xFFFFu, q = pq >> 16;

    float4   A  = g_ck[2 * sl * H + p];
    float4   Bv = g_ck[2 * sl * H + q];
    unsigned ia = g_ik[2 * sl * H + p];
    unsigned ib = g_ik[2 * sl * H + q];

    float al[4] = {A.x, A.y, A.z, A.w};
    float be[4] = {Bv.x, Bv.y, Bv.z, Bv.w};

#pragma unroll
    for (int m2 = 0; m2 < 4; m2++)
#pragma unroll
        for (int m1 = 0; m1 < 4; m1++) {
            float cv = e.w * al[m1] * be[m2];
            if (m2 == 0) cv += e.y * al[m1];
            if (m1 == 0) cv += e.z * be[m2];
            if (m1 == 0 && m2 == 0) cv += e.x;
            g_fkc_raw[g * 16 + (m1 | (m2 << 2))] = cv;
        }
    g_fki[g] = make_uint2(ia, ib);
}

// ---------------------------------------------------------------------------
// Kernel S1: greedy bank schedule (integer only; bank tables in shared mem).
// Layer1 (sl=0): leaves with idx<1024 are n-leaves -> register-fed, no bank
// cost; h-leaves (idx>=1024): copy0 addr=idx, copy1 addr=2048+j+(j>>5), j=idx-1024.
// Layer2 (sl=1): copy0 addr=idx, copy1 addr=1024+idx+(idx>>5).
// Any assignment is CORRECT; only bank-conflict speed is affected.
// ---------------------------------------------------------------------------
__global__ void schedule_k()
{
    __shared__ int loads_s[64][4][32];
    int id = threadIdx.x;
    if (id >= 64) return;
    int sl = id >> 5, w = id & 31;
    int (*loads)[32] = loads_s[id];
#pragma unroll
    for (int s = 0; s < 4; s++)
        for (int b = 0; b < 32; b++) loads[s][b] = 0;

    for (int lane = 0; lane < 32; lane++) {
        int gate = sl * H + w * 32 + lane;
        uint2 ri = g_fki[gate];
        int idx[4] = { (int)(ri.x & 0xFFFFu), (int)(ri.x >> 16),
                       (int)(ri.y & 0xFFFFu), (int)(ri.y >> 16) };
        int slotOfVar[4], addrSlot[4] = {0,0,0,0}, idxSlot[4] = {0,0,0,0};
        unsigned used = 0, nmask = 0;

        // pass 0: smem-backed leaves
        for (int t = 0; t < 4; t++) {
            bool isn = (sl == 0) && (idx[t] < 1024);
            if (isn) continue;
            int best = 1 << 30, bs = 0, ba = idx[t];
            for (int s = 0; s < 4; s++) {
                if ((used >> s) & 1) continue;
                for (int cp = 0; cp < 2; cp++) {
                    int a;
                    if (sl == 0) { int j = idx[t] - 1024;
                                   a = cp ? (2048 + j + (j >> 5)) : idx[t]; }
                    else         { a = cp ? (1024 + idx[t] + (idx[t] >> 5)) : idx[t]; }
                    int ld = loads[s][a & 31];
                    if (ld < best) { best = ld; bs = s; ba = a; }
                }
            }
            used |= 1u << bs; slotOfVar[t] = bs; addrSlot[bs] = ba;
            loads[bs][ba & 31]++;
        }
        // pass 1: n-leaves fill remaining slots
        for (int t = 0; t < 4; t++) {
            bool isn = (sl == 0) && (idx[t] < 1024);
            if (!isn) continue;
            int s = 0; while ((used >> s) & 1) s++;
            used |= 1u << s; slotOfVar[t] = s; nmask |= 1u << s; idxSlot[s] = idx[t];
        }

        g_fka[gate] = make_uint2((unsigned)addrSlot[0] | ((unsigned)addrSlot[1] << 16),
                                 (unsigned)addrSlot[2] | ((unsigned)addrSlot[3] << 16));
        g_msk[gate] = nmask;
        unsigned perm = 0;
        for (int t = 0; t < 4; t++) perm |= (unsigned)t << (2 * slotOfVar[t]);
        g_perm[gate] = perm;
        g_l1i[gate] = make_uint2((unsigned)idxSlot[0] | ((unsigned)idxSlot[1] << 16),
                                 (unsigned)idxSlot[2] | ((unsigned)idxSlot[3] << 16));
    }
}

// ---------------------------------------------------------------------------
// Kernel S2: permute coeffs into slot basis (fully parallel, 1 thread/coeff)
// ---------------------------------------------------------------------------
__global__ void permute_coef()
{
    int id = blockIdx.x * blockDim.x + threadIdx.x;
    if (id >= 2 * H * 16) return;
    int gate = id >> 4, m = id & 15;
    unsigned perm = g_perm[gate];
    int om = 0;
#pragma unroll
    for (int s = 0; s < 4; s++)
        if ((m >> s) & 1) om |= 1 << ((perm >> (2 * s)) & 3);
    ((float*)g_fkc)[gate * 16 + m] = g_fkc_raw[gate * 16 + om];
}

// ---------------------------------------------------------------------------
// Kernel S3: build per-token layer-1 n-leaf table in slot order.
// ---------------------------------------------------------------------------
__global__ void build_nleaf()
{
    int id = blockIdx.x * blockDim.x + threadIdx.x;
    if (id >= VV * H) return;
    int v = id >> 10, g1 = id & (H - 1);
    unsigned msk = g_msk[g1];
    uint2 ii = g_l1i[g1];
    const float* nrow = g_ntab + v * H;
    float4 r = make_float4(0.f, 0.f, 0.f, 0.f);
    if (msk & 1u) r.x = nrow[ii.x & 0xFFFFu];
    if (msk & 2u) r.y = nrow[ii.x >> 16];
    if (msk & 4u) r.z = nrow[ii.y & 0xFFFFu];
    if (msk & 8u) r.w = nrow[ii.y >> 16];
    g_nleaf[id] = r;
}

// ---------------------------------------------------------------------------
// Multilinear super-gate evals
// ---------------------------------------------------------------------------
__device__ __forceinline__ float poly16(const float4* c, float v0, float v1,
                                        float v2, float v3)
{
    float p01 = v0 * v1, p23 = v2 * v3;
    float r0 = fmaf(c[0].w, p01, fmaf(c[0].z, v1, fmaf(c[0].y, v0, c[0].x)));
    float r1 = fmaf(c[1].w, p01, fmaf(c[1].z, v1, fmaf(c[1].y, v0, c[1].x)));
    float r2 = fmaf(c[2].w, p01, fmaf(c[2].z, v1, fmaf(c[2].y, v0, c[2].x)));
    float r3 = fmaf(c[3].w, p01, fmaf(c[3].z, v1, fmaf(c[3].y, v0, c[3].x)));
    return fmaf(p23, r3, fmaf(v3, r2, fmaf(v2, r1, r0)));
}

__device__ __forceinline__ float eval16(const float4* c, uint2 ad, const float* base)
{
    float v0 = base[ad.x & 0xFFFFu], v1 = base[ad.x >> 16];
    float v2 = base[ad.y & 0xFFFFu], v3 = base[ad.y >> 16];
    return poly16(c, v0, v1, v2, v3);
}

__device__ __forceinline__ float eval16_mix(const float4* c, uint2 ad,
                                            unsigned msk, float4 nf,
                                            const float* base)
{
    float v0, v1, v2, v3;
    if (msk & 1u) v0 = nf.x; else v0 = base[ad.x & 0xFFFFu];
    if (msk & 2u) v1 = nf.y; else v1 = base[ad.x >> 16];
    if (msk & 4u) v2 = nf.z; else v2 = base[ad.y & 0xFFFFu];
    if (msk & 8u) v3 = nf.w; else v3 = base[ad.y >> 16];
    return poly16(c, v0, v1, v2, v3);
}

// ---------------------------------------------------------------------------
// Kernel C: per-row recurrence (one CTA per batch row) + m-block + logit
// ---------------------------------------------------------------------------
__global__ __launch_bounds__(H, 1) void recur_kernel(
    const int* __restrict__ x, const int* __restrict__ last_index,
    const float* __restrict__ rec_w, const float* __restrict__ rec_b,
    float* __restrict__ out)
{
    __shared__ float comb_all[COMB_ALL_SZ];
    __shared__ float t_all[T_ALL_SZ];
    __shared__ int   tok[SS];
    __shared__ float red[32];

    int b = blockIdx.x, tid = threadIdx.x;

    float4 c0[4], c1[4];
#pragma unroll
    for (int j = 0; j < 4; j++) { c0[j] = g_fkc[tid * 4 + j]; c1[j] = g_fkc[(H + tid) * 4 + j]; }
    uint2    a0   = g_fka[tid], a1 = g_fka[H + tid];
    unsigned msk0 = g_msk[tid];

    const int sk = tid + (tid >> 5);

    comb_all[1024 + tid] = 0.f;     // h copy0
    comb_all[2048 + sk]  = 0.f;     // h copy1 (skewed)
    if (tid < SS) tok[tid] = x[b * SS + tid];
    int li = last_index[b];
    __syncthreads();

    if (li > 0) {
        float4 nf4 = g_nleaf[tok[0] * H + tid];
        for (int t = 0; t < li - 1; t++) {
            float4 nx = g_nleaf[tok[t + 1] * H + tid];      // prefetch (L2)
            float u = eval16_mix(c0, a0, msk0, nf4, comb_all);
            t_all[tid] = u;  t_all[1024 + sk] = u;
            __syncthreads();
            float v = eval16(c1, a1, t_all);
            comb_all[1024 + tid] = v;  comb_all[2048 + sk] = v;
            __syncthreads();
            nf4 = nx;
        }
        comb_all[tid] = g_ntab[tok[li - 1] * H + tid];      // n for m-block
    } else {
        comb_all[tid] = 0.f;
    }
    __syncthreads();

    // ---- m block (once per row; reads comb_all[0..2047] = [n | h]) ----
    float* mA = t_all;
    float* mB = t_all + 1024;
    {
        float4 c; unsigned pi; float a, bb;
        c = g_cm[tid];        pi = g_im[tid];
        a = comb_all[pi & 0xFFFFu]; bb = comb_all[pi >> 16];
        mA[tid] = fmaf(c.w, a * bb, fmaf(c.z, bb, fmaf(c.y, a, c.x)));
        __syncthreads();
        c = g_cm[H + tid];    pi = g_im[H + tid];
        a = mA[pi & 0xFFFFu];  bb = mA[pi >> 16];
        mB[tid] = fmaf(c.w, a * bb, fmaf(c.z, bb, fmaf(c.y, a, c.x)));
        __syncthreads();
        c = g_cm[2*H + tid];  pi = g_im[2*H + tid];
        a = mB[pi & 0xFFFFu];  bb = mB[pi >> 16];
        mA[tid] = fmaf(c.w, a * bb, fmaf(c.z, bb, fmaf(c.y, a, c.x)));
        __syncthreads();
        c = g_cm[3*H + tid];  pi = g_im[3*H + tid];
        a = mA[pi & 0xFFFFu];  bb = mA[pi >> 16];
        mB[tid] = fmaf(c.w, a * bb, fmaf(c.z, bb, fmaf(c.y, a, c.x)));
        __syncthreads();
    }

    // ---- final layer (2048 gates, 2 per thread) + GF-sum + dot(rec_w) ----
    float4   cA = g_cmf[2 * tid],     cB = g_cmf[2 * tid + 1];
    unsigned pA = g_imf[2 * tid],     pB = g_imf[2 * tid + 1];
    float aA = mB[pA & 0xFFFFu], bA = mB[pA >> 16];
    float vA = fmaf(cA.w, aA * bA, fmaf(cA.z, bA, fmaf(cA.y, aA, cA.x)));
    float aB = mB[pB & 0xFFFFu], bB = mB[pB >> 16];
    float vB = fmaf(cB.w, aB * bB, fmaf(cB.z, bB, fmaf(cB.y, aB, cB.x)));
    float acc = (vA + vB) * rec_w[tid];

#pragma unroll
    for (int o = 16; o > 0; o >>= 1) acc += __shfl_xor_sync(0xFFFFFFFFu, acc, o);
    int warp = tid >> 5, lane = tid & 31;
    if (lane == 0) red[warp] = acc;
    __syncthreads();
    if (tid < 32) {
        float r = red[tid];
#pragma unroll
        for (int o = 16; o > 0; o >>= 1) r += __shfl_xor_sync(0xFFFFFFFFu, r, o);
        if (tid == 0) out[b] = r + rec_b[0];
    }
}

// ---------------------------------------------------------------------------
// kernel_launch
// ---------------------------------------------------------------------------
extern "C" void kernel_launch(void* const* d_in, const int* in_sizes, int n_in,
                              void* d_out, int out_size)
{
    const int*   x          = (const int*)  d_in[0];
    const int*   last_index = (const int*)  d_in[1];
    const float* emb_table  = (const float*)d_in[3];
    const float* n_w        = (const float*)d_in[4];
    const float* k_w        = (const float*)d_in[5];
    const float* m_w        = (const float*)d_in[6];
    const float* mf_w       = (const float*)d_in[7];
    const float* rec_w      = (const float*)d_in[8];
    const float* rec_b      = (const float*)d_in[9];
    const int*   n_idx      = (const int*)  d_in[10];
    const int*   k_idx0     = (const int*)  d_in[11];
    const int*   k_idx_rest = (const int*)  d_in[12];
    const int*   m_idx0     = (const int*)  d_in[13];
    const int*   m_idx_rest = (const int*)  d_in[14];
    const int*   m_idx_fin  = (const int*)  d_in[15];

    const int NG = 3 * LL * H + 2 * H;
    precompute_coef<<<(NG + 255) / 256, 256>>>(
        n_w, k_w, m_w, mf_w, n_idx, k_idx0, k_idx_rest, m_idx0, m_idx_rest, m_idx_fin);
    precompute_ntab<<<VV, H>>>(emb_table);
    fuse_k<<<(2 * H + 255) / 256, 256>>>();
    schedule_k<<<1, 64>>>();
    permute_coef<<<(2 * H * 16 + 255) / 256, 256>>>();
    build_nleaf<<<(VV * H + 255) / 256, 256>>>();
    recur_kernel<<<BB, H>>>(x, last_index, rec_w, rec_b, (float*)d_out);
}

// round 4
// speedup vs baseline: 1.4234x; 1.4234x over previous
#include <cuda_runtime.h>
#include <cstdint>

// Problem constants (fixed by the dataset)
#define H   1024
#define LL  4
#define BB  128
#define SS  512
#define VV  128

// Dual-copy shared layouts in recur_kernel (same as Round-2 winner):
//  comb_all: [0,2048) copy0 = [n | h]; [2048, 2048+2112) copy1 skewed (addr = 2048 + i + (i>>5))
//  t_all:    [0,1024) copy0;           [1024, 1024+1056) copy1 skewed (addr = 1024 + i + (i>>5))
#define COMB_ALL_SZ 4160
#define T_ALL_SZ    2080

// ---------------------------------------------------------------------------
// Scratch (device globals — no allocation allowed in kernel_launch)
// ---------------------------------------------------------------------------
__device__ float4   g_cn [LL*H];
__device__ float4   g_ck [LL*H];
__device__ float4   g_cm [LL*H];
__device__ float4   g_cmf[2*H];
__device__ unsigned g_in [LL*H];
__device__ unsigned g_ik [LL*H];
__device__ unsigned g_im [LL*H];
__device__ unsigned g_imf[2*H];
__device__ float    g_ntab[VV*H];      // n-branch output per token

// Fused k super-layers
__device__ float    g_fkc_raw[2*H*16]; // canonical multilinear coeffs
__device__ uint2    g_fki[2*H];        // raw logical indices (4 x 16-bit)
__device__ float4   g_fkc[2*H*4];      // slot-permuted coeffs (final)
__device__ uint2    g_fka[2*H];        // physical smem addresses (4 x 16-bit)
__device__ unsigned g_perm[2*H];       // varOfSlot, 2 bits per slot

// ---------------------------------------------------------------------------
// Kernel A: softmax(w) -> affine gate coefficients, pack gather indices.
// Gate basis: out = c0 + c1*a + c2*b + c3*a*b
// ---------------------------------------------------------------------------
__global__ void precompute_coef(
    const float* __restrict__ n_w, const float* __restrict__ k_w,
    const float* __restrict__ m_w, const float* __restrict__ mf_w,
    const int* __restrict__ n_idx, const int* __restrict__ k_idx0,
    const int* __restrict__ k_idx_rest, const int* __restrict__ m_idx0,
    const int* __restrict__ m_idx_rest, const int* __restrict__ m_idx_fin)
{
    int g = blockIdx.x * blockDim.x + threadIdx.x;
    const int NG = 3 * LL * H + 2 * H;   // 14336
    if (g >= NG) return;

    const float* w; int i0, i1; float4* cdst; unsigned* idst; int slot;
    if (g < LL * H) {
        int l = g >> 10, o = g & (H - 1);
        w = n_w + (l * H + o) * 16;
        i0 = n_idx[(l * 2 + 0) * H + o];
        i1 = n_idx[(l * 2 + 1) * H + o];
        cdst = g_cn; idst = g_in; slot = g;
    } else if (g < 2 * LL * H) {
        int gg = g - LL * H, l = gg >> 10, o = gg & (H - 1);
        w = k_w + (l * H + o) * 16;
        if (l == 0) { i0 = k_idx0[o]; i1 = k_idx0[H + o]; }
        else        { i0 = k_idx_rest[((l - 1) * 2 + 0) * H + o];
                      i1 = k_idx_rest[((l - 1) * 2 + 1) * H + o]; }
        cdst = g_ck; idst = g_ik; slot = gg;
    } else if (g < 3 * LL * H) {
        int gg = g - 2 * LL * H, l = gg >> 10, o = gg & (H - 1);
        w = m_w + (l * H + o) * 16;
        if (l == 0) { i0 = m_idx0[o]; i1 = m_idx0[H + o]; }
        else        { i0 = m_idx_rest[((l - 1) * 2 + 0) * H + o];
                      i1 = m_idx_rest[((l - 1) * 2 + 1) * H + o]; }
        cdst = g_cm; idst = g_im; slot = gg;
    } else {
        int j = g - 3 * LL * H;               // 0..2047
        w = mf_w + j * 16;
        i0 = m_idx_fin[j]; i1 = m_idx_fin[2 * H + j];
        cdst = g_cmf; idst = g_imf; slot = j;
    }

    float p[16], mx = w[0];
#pragma unroll
    for (int i = 1; i < 16; i++) mx = fmaxf(mx, w[i]);
    float s = 0.f;
#pragma unroll
    for (int i = 0; i < 16; i++) { p[i] = expf(w[i] - mx); s += p[i]; }
    float inv = 1.0f / s;
#pragma unroll
    for (int i = 0; i < 16; i++) p[i] *= inv;

    float c0 = p[8] + p[9] + p[10] + p[11] + p[12] + p[13] + p[14] + p[15];
    float c1 = p[2] + p[3] + p[6] + p[7] - p[8] - p[9] - p[12] - p[13];
    float c2 = p[4] + p[5] + p[6] + p[7] - p[8] - p[9] - p[10] - p[11];
    float c3 = p[1] - p[2] - p[4] - 2.f * p[6] - p[7]
             + p[8] + 2.f * p[9] + p[11] + p[13] - p[14];

    cdst[slot] = make_float4(c0, c1, c2, c3);
    idst[slot] = (unsigned)i0 | ((unsigned)i1 << 16);
}

// ---------------------------------------------------------------------------
// Kernel B: N_table[v] = n-branch(sigmoid(emb_table[v]))
// ---------------------------------------------------------------------------
__global__ __launch_bounds__(H) void precompute_ntab(const float* __restrict__ emb_table)
{
    __shared__ float b0[H], b1[H];
    int v = blockIdx.x, tid = threadIdx.x;
    float e = emb_table[v * H + tid];            // E == H == 1024
    b0[tid] = 1.0f / (1.0f + expf(-e));
    __syncthreads();
    float* src = b0; float* dst = b1;
#pragma unroll
    for (int l = 0; l < LL; l++) {
        float4  c  = g_cn[l * H + tid];
        unsigned pi = g_in[l * H + tid];
        float a = src[pi & 0xFFFFu], b = src[pi >> 16];
        dst[tid] = fmaf(c.w, a * b, fmaf(c.z, b, fmaf(c.y, a, c.x)));
        __syncthreads();
        float* t = src; src = dst; dst = t;
    }
    g_ntab[v * H + tid] = src[tid];
}

// ---------------------------------------------------------------------------
// Kernel F: fuse k-layer pairs (0,1) and (2,3) into multilinear super-gates.
// ---------------------------------------------------------------------------
__global__ void fuse_k()
{
    int g = blockIdx.x * blockDim.x + threadIdx.x;
    if (g >= 2 * H) return;
    int sl = g >> 10, o = g & (H - 1);

    float4   e  = g_ck[(2 * sl + 1) * H + o];
    unsigned pq = g_ik[(2 * sl + 1) * H + o];
    int p = pq & 0xFFFFu, q = pq >> 16;

    float4   A  = g_ck[2 * sl * H + p];
    float4   Bv = g_ck[2 * sl * H + q];
    unsigned ia = g_ik[2 * sl * H + p];
    unsigned ib = g_ik[2 * sl * H + q];

    float al[4] = {A.x, A.y, A.z, A.w};
    float be[4] = {Bv.x, Bv.y, Bv.z, Bv.w};

#pragma unroll
    for (int m2 = 0; m2 < 4; m2++)
#pragma unroll
        for (int m1 = 0; m1 < 4; m1++) {
            float cv = e.w * al[m1] * be[m2];
            if (m2 == 0) cv += e.y * al[m1];
            if (m1 == 0) cv += e.z * be[m2];
            if (m1 == 0 && m2 == 0) cv += e.x;
            g_fkc_raw[g * 16 + (m1 | (m2 << 2))] = cv;
        }
    g_fki[g] = make_uint2(ia, ib);
}

// ---------------------------------------------------------------------------
// Kernel S1: warp-parallel greedy bank scheduler. One task (layer sl, warp w)
// per CTA: grid=64, block=32. Lane b holds cnt[s] (4 registers) = number of
// loads already assigned to (slot s, bank b). For each gate (lane l, leaf t),
// the candidate costs for (4 slots x 2 copies) are fetched via shuffles and
// the argmin is computed redundantly on all lanes (same visit order and
// tie-breaking as the Round-2 serial greedy -> identical schedule).
// Any schedule is CORRECT; it only affects bank-conflict speed.
// ---------------------------------------------------------------------------
__global__ __launch_bounds__(32) void schedule_k_fast()
{
    const unsigned FULL = 0xFFFFFFFFu;
    int task = blockIdx.x;               // 0..63
    int sl = task >> 5, w = task & 31;
    int lane = threadIdx.x;
    int gate = sl * H + w * 32 + lane;
    uint2 ri = g_fki[gate];
    int dom = (sl == 0) ? 2048 : 1024;   // copy1 base offset

    int cnt0 = 0, cnt1 = 0, cnt2 = 0, cnt3 = 0;   // bank=lane, slots 0..3
    unsigned myLo = 0, myHi = 0, myPerm = 0;

    for (int l = 0; l < 32; l++) {
        unsigned rx = __shfl_sync(FULL, ri.x, l);
        unsigned ry = __shfl_sync(FULL, ri.y, l);
        int idxs[4] = { (int)(rx & 0xFFFFu), (int)(rx >> 16),
                        (int)(ry & 0xFFFFu), (int)(ry >> 16) };
        unsigned used = 0, perm = 0;
        int aS0 = 0, aS1 = 0, aS2 = 0, aS3 = 0;
#pragma unroll
        for (int t = 0; t < 4; t++) {
            int id0 = idxs[t];
            int A0 = id0;
            int A1 = dom + id0 + (id0 >> 5);
            int b0 = A0 & 31, b1 = A1 & 31;
            int c00 = __shfl_sync(FULL, cnt0, b0);
            int c01 = __shfl_sync(FULL, cnt1, b0);
            int c02 = __shfl_sync(FULL, cnt2, b0);
            int c03 = __shfl_sync(FULL, cnt3, b0);
            int c10 = __shfl_sync(FULL, cnt0, b1);
            int c11 = __shfl_sync(FULL, cnt1, b1);
            int c12 = __shfl_sync(FULL, cnt2, b1);
            int c13 = __shfl_sync(FULL, cnt3, b1);
            // visit order (s0,cp0),(s0,cp1),(s1,cp0),... with strict '<'
            // == Round-2 serial greedy order
            int best = 1 << 30, bs = 0, bcp = 0;
            if (!(used & 1u)) { if (c00 < best) { best = c00; bs = 0; bcp = 0; }
                                if (c10 < best) { best = c10; bs = 0; bcp = 1; } }
            if (!(used & 2u)) { if (c01 < best) { best = c01; bs = 1; bcp = 0; }
                                if (c11 < best) { best = c11; bs = 1; bcp = 1; } }
            if (!(used & 4u)) { if (c02 < best) { best = c02; bs = 2; bcp = 0; }
                                if (c12 < best) { best = c12; bs = 2; bcp = 1; } }
            if (!(used & 8u)) { if (c03 < best) { best = c03; bs = 3; bcp = 0; }
                                if (c13 < best) { best = c13; bs = 3; bcp = 1; } }
            used |= 1u << bs;
            int aw = bcp ? A1 : A0;
            int bw = bcp ? b1 : b0;
            if (bs == 0) aS0 = aw; else if (bs == 1) aS1 = aw;
            else if (bs == 2) aS2 = aw; else aS3 = aw;
            perm |= (unsigned)t << (2 * bs);
            if (lane == bw) {
                if      (bs == 0) cnt0++;
                else if (bs == 1) cnt1++;
                else if (bs == 2) cnt2++;
                else              cnt3++;
            }
        }
        if (lane == l) {
            myLo = (unsigned)aS0 | ((unsigned)aS1 << 16);
            myHi = (unsigned)aS2 | ((unsigned)aS3 << 16);
            myPerm = perm;
        }
    }
    g_fka[gate]  = make_uint2(myLo, myHi);
    g_perm[gate] = myPerm;
}

// ---------------------------------------------------------------------------
// Kernel S2: permute coeffs into slot basis (fully parallel, 1 thread/coeff)
// ---------------------------------------------------------------------------
__global__ void permute_coef()
{
    int id = blockIdx.x * blockDim.x + threadIdx.x;
    if (id >= 2 * H * 16) return;
    int gate = id >> 4, m = id & 15;
    unsigned perm = g_perm[gate];
    int om = 0;
#pragma unroll
    for (int s = 0; s < 4; s++)
        if ((m >> s) & 1) om |= 1 << ((perm >> (2 * s)) & 3);
    ((float*)g_fkc)[gate * 16 + m] = g_fkc_raw[gate * 16 + om];
}

// ---------------------------------------------------------------------------
// Multilinear super-gate eval
// ---------------------------------------------------------------------------
__device__ __forceinline__ float eval16(const float4* c, uint2 ad, const float* base)
{
    float v0 = base[ad.x & 0xFFFFu], v1 = base[ad.x >> 16];
    float v2 = base[ad.y & 0xFFFFu], v3 = base[ad.y >> 16];
    float p01 = v0 * v1, p23 = v2 * v3;
    float r0 = fmaf(c[0].w, p01, fmaf(c[0].z, v1, fmaf(c[0].y, v0, c[0].x)));
    float r1 = fmaf(c[1].w, p01, fmaf(c[1].z, v1, fmaf(c[1].y, v0, c[1].x)));
    float r2 = fmaf(c[2].w, p01, fmaf(c[2].z, v1, fmaf(c[2].y, v0, c[2].x)));
    float r3 = fmaf(c[3].w, p01, fmaf(c[3].z, v1, fmaf(c[3].y, v0, c[3].x)));
    return fmaf(p23, r3, fmaf(v3, r2, fmaf(v2, r1, r0)));
}

// ---------------------------------------------------------------------------
// Kernel C: per-row recurrence (one CTA per batch row) + m-block + logit
// (identical to the Round-2 winner)
// ---------------------------------------------------------------------------
__global__ __launch_bounds__(H, 1) void recur_kernel(
    const int* __restrict__ x, const int* __restrict__ last_index,
    const float* __restrict__ rec_w, const float* __restrict__ rec_b,
    float* __restrict__ out)
{
    __shared__ float comb_all[COMB_ALL_SZ];
    __shared__ float t_all[T_ALL_SZ];
    __shared__ int   tok[SS];
    __shared__ float red[32];

    int b = blockIdx.x, tid = threadIdx.x;

    float4 c0[4], c1[4];
#pragma unroll
    for (int j = 0; j < 4; j++) { c0[j] = g_fkc[tid * 4 + j]; c1[j] = g_fkc[(H + tid) * 4 + j]; }
    uint2 a0 = g_fka[tid], a1 = g_fka[H + tid];

    const int sk = tid + (tid >> 5);   // skew offset for index tid

    comb_all[tid] = 0.f; comb_all[1024 + tid] = 0.f;
    if (tid < SS) tok[tid] = x[b * SS + tid];
    int li = last_index[b];
    __syncthreads();

    if (li > 0) {
        float nf0 = g_ntab[tok[0] * H + tid];
        comb_all[tid] = nf0;             comb_all[2048 + sk] = nf0;
        comb_all[1024 + tid] = 0.f;      comb_all[3104 + sk] = 0.f;
        __syncthreads();

        for (int t = 0; t < li - 1; t++) {
            float nf = g_ntab[tok[t + 1] * H + tid];      // prefetch next n-row
            float u = eval16(c0, a0, comb_all);           // super-layer 1
            t_all[tid] = u;  t_all[1024 + sk] = u;
            __syncthreads();
            float v = eval16(c1, a1, t_all);              // super-layer 2
            comb_all[1024 + tid] = v;  comb_all[3104 + sk] = v;   // h_{t+1}
            comb_all[tid]        = nf; comb_all[2048 + sk] = nf;  // n_{t+1}
            __syncthreads();
        }
        // comb copy0 now holds [n_{li-1}, h_{li-1}]
    }
    // li == 0: comb copy0 stays all-zero -> init_out path (matches reference)

    // ---- m block (once per row, reads copy0 only) ----
    float* mA = t_all;            // [0,1024)
    float* mB = t_all + 1024;     // [1024,2048)
    {
        float4 c; unsigned pi; float a, bb;
        c = g_cm[tid];        pi = g_im[tid];
        a = comb_all[pi & 0xFFFFu]; bb = comb_all[pi >> 16];
        mA[tid] = fmaf(c.w, a * bb, fmaf(c.z, bb, fmaf(c.y, a, c.x)));
        __syncthreads();
        c = g_cm[H + tid];    pi = g_im[H + tid];
        a = mA[pi & 0xFFFFu];  bb = mA[pi >> 16];
        mB[tid] = fmaf(c.w, a * bb, fmaf(c.z, bb, fmaf(c.y, a, c.x)));
        __syncthreads();
        c = g_cm[2*H + tid];  pi = g_im[2*H + tid];
        a = mB[pi & 0xFFFFu];  bb = mB[pi >> 16];
        mA[tid] = fmaf(c.w, a * bb, fmaf(c.z, bb, fmaf(c.y, a, c.x)));
        __syncthreads();
        c = g_cm[3*H + tid];  pi = g_im[3*H + tid];
        a = mA[pi & 0xFFFFu];  bb = mA[pi >> 16];
        mB[tid] = fmaf(c.w, a * bb, fmaf(c.z, bb, fmaf(c.y, a, c.x)));
        __syncthreads();
    }

    // ---- final layer (2048 gates, 2 per thread) + GF-sum + dot(rec_w) ----
    float4   cA = g_cmf[2 * tid],     cB = g_cmf[2 * tid + 1];
    unsigned pA = g_imf[2 * tid],     pB = g_imf[2 * tid + 1];
    float aA = mB[pA & 0xFFFFu], bA = mB[pA >> 16];
    float vA = fmaf(cA.w, aA * bA, fmaf(cA.z, bA, fmaf(cA.y, aA, cA.x)));
    float aB = mB[pB & 0xFFFFu], bB = mB[pB >> 16];
    float vB = fmaf(cB.w, aB * bB, fmaf(cB.z, bB, fmaf(cB.y, aB, cB.x)));
    float acc = (vA + vB) * rec_w[tid];   // GF=2: both gates map to rec_w[tid]

#pragma unroll
    for (int o = 16; o > 0; o >>= 1) acc += __shfl_xor_sync(0xFFFFFFFFu, acc, o);
    int warp = tid >> 5, lane = tid & 31;
    if (lane == 0) red[warp] = acc;
    __syncthreads();
    if (tid < 32) {
        float r = red[tid];
#pragma unroll
        for (int o = 16; o > 0; o >>= 1) r += __shfl_xor_sync(0xFFFFFFFFu, r, o);
        if (tid == 0) out[b] = r + rec_b[0];
    }
}

// ---------------------------------------------------------------------------
// kernel_launch
// ---------------------------------------------------------------------------
extern "C" void kernel_launch(void* const* d_in, const int* in_sizes, int n_in,
                              void* d_out, int out_size)
{
    const int*   x          = (const int*)  d_in[0];
    const int*   last_index = (const int*)  d_in[1];
    // d_in[2] = positive_mask (unused by the reference output)
    const float* emb_table  = (const float*)d_in[3];
    const float* n_w        = (const float*)d_in[4];
    const float* k_w        = (const float*)d_in[5];
    const float* m_w        = (const float*)d_in[6];
    const float* mf_w       = (const float*)d_in[7];
    const float* rec_w      = (const float*)d_in[8];
    const float* rec_b      = (const float*)d_in[9];
    const int*   n_idx      = (const int*)  d_in[10];
    const int*   k_idx0     = (const int*)  d_in[11];
    const int*   k_idx_rest = (const int*)  d_in[12];
    const int*   m_idx0     = (const int*)  d_in[13];
    const int*   m_idx_rest = (const int*)  d_in[14];
    const int*   m_idx_fin  = (const int*)  d_in[15];

    const int NG = 3 * LL * H + 2 * H;   // 14336
    precompute_coef<<<(NG + 255) / 256, 256>>>(
        n_w, k_w, m_w, mf_w, n_idx, k_idx0, k_idx_rest, m_idx0, m_idx_rest, m_idx_fin);
    precompute_ntab<<<VV, H>>>(emb_table);
    fuse_k<<<(2 * H + 255) / 256, 256>>>();
    schedule_k_fast<<<64, 32>>>();
    permute_coef<<<(2 * H * 16 + 255) / 256, 256>>>();
    recur_kernel<<<BB, H>>>(x, last_index, rec_w, rec_b, (float*)d_out);
}